// round 11
// baseline (speedup 1.0000x reference)
#include <cuda_runtime.h>
#include <cstdint>
#include <cfloat>
#include <cmath>

// Problem shape (fixed by reference)
constexpr int BB = 8, NN = 8192, LL = 1024, DD = 128;
constexpr int M_TOTAL = BB * NN;            // 65536 rows
constexpr int BM = 64, BK = 32;
constexpr int NK = LL / BK;                 // 32 k-tiles
constexpr int XS_STR = 36;                  // 4g+t distinct mod 32 -> conflict-free A-frag LDS
constexpr int WS_STR = 136;                 // 8t+g distinct mod 32 -> conflict-free B-frag LDS
constexpr int XS_ELEMS = 2 * BM * XS_STR;   // 4608 words
constexpr int WS_ELEMS = 2 * BK * WS_STR;   // 8704 words
constexpr int SMEM_WORDS = XS_ELEMS + 2 * WS_ELEMS + DD + BM * 4;
constexpr int SMEM_BYTES = SMEM_WORDS * 4;  // 89600 B -> 2 CTAs/SM

constexpr int CHUNKS = 16;                  // n-chunks per batch for deterministic pooling

// Scratch (no allocation allowed in kernel_launch)
__device__ float g_logits[M_TOTAL];
__device__ float g_weights[M_TOTAL];
__device__ float g_partial[BB * CHUNKS * LL];
__device__ int   g_mask_mode;               // 0=int32, 1=float32, 2=int8

__device__ __forceinline__ void cp_async16(uint32_t s, const void* g) {
    asm volatile("cp.async.cg.shared.global [%0], [%1], 16;\n" :: "r"(s), "l"(g));
}

__device__ __forceinline__ void mma_tf32(float* c, const uint32_t* a, const uint32_t* b) {
    asm volatile(
        "mma.sync.aligned.m16n8k8.row.col.f32.tf32.tf32.f32 "
        "{%0,%1,%2,%3}, {%4,%5,%6,%7}, {%8,%9}, {%0,%1,%2,%3};\n"
        : "+f"(c[0]), "+f"(c[1]), "+f"(c[2]), "+f"(c[3])
        : "r"(a[0]), "r"(a[1]), "r"(a[2]), "r"(a[3]), "r"(b[0]), "r"(b[1]));
}

// ---------------------------------------------------------------------------
// Phase 0: detect the mask dtype from its bit pattern (deterministic).
// Scan the first 16384 32-bit words (64 KB = full buffer if int8, first
// quarter if int32/float32). Mask semantics guarantee runs of >=4096
// consecutive 1s per batch, so:
//   all words in {0,1}        -> int32 (mode 0)
//   any word == 0x3F800000   -> float32 (mode 1)
//   otherwise                 -> int8  (mode 2)
// ---------------------------------------------------------------------------
__global__ void detect_mask_kernel(const uint32_t* __restrict__ m)
{
    __shared__ int s_non01, s_f32;
    if (threadIdx.x == 0) { s_non01 = 0; s_f32 = 0; }
    __syncthreads();
    int non01 = 0, isf32 = 0;
    for (int i = threadIdx.x; i < 16384; i += blockDim.x) {
        const uint32_t w = m[i];
        if (w > 1u) non01 = 1;
        if (w == 0x3F800000u) isf32 = 1;
    }
    if (non01) atomicOr(&s_non01, 1);
    if (isf32) atomicOr(&s_f32, 1);
    __syncthreads();
    if (threadIdx.x == 0)
        g_mask_mode = (!s_non01) ? 0 : (s_f32 ? 1 : 2);
}

__device__ __forceinline__ bool is_pad(const void* mask, int mode, int idx) {
    if (mode == 0) return ((const int*)mask)[idx] != 0;
    if (mode == 1) return ((const float*)mask)[idx] != 0.0f;
    return ((const unsigned char*)mask)[idx] != 0;
}

// ---------------------------------------------------------------------------
// Phase 1: fused  Ca = X@Wa, Cb = X@Wb, logit = (tanh(Ca)*sigmoid(Cb)) @ Wc
// Grid: 1024 CTAs x 256 thr. CTA tile: 64(M) x 128(D) x full K=1024.
// 8 warps as 2(M) x 4(N), each warp 32x32 per GEMM.
// ---------------------------------------------------------------------------
__global__ void __launch_bounds__(256, 2)
gemm_logits_kernel(const float* __restrict__ X, const float* __restrict__ Wa,
                   const float* __restrict__ Wb, const float* __restrict__ Wc)
{
    extern __shared__ uint32_t sm[];
    uint32_t* Xs  = sm;                       // [2][64][36]
    uint32_t* Was = sm + XS_ELEMS;            // [2][32][136]
    uint32_t* Wbs = Was + WS_ELEMS;           // [2][32][136]
    float* Wc_s   = (float*)(Wbs + WS_ELEMS); // [128]
    float* red    = Wc_s + DD;                // [64][4]

    const int tid  = threadIdx.x;
    const int lane = tid & 31;
    const int warp = tid >> 5;
    const int g = lane >> 2, t = lane & 3;
    const int wm = warp >> 2, wn = warp & 3;
    const int row_base = blockIdx.x * BM;

    if (tid < DD) Wc_s[tid] = Wc[tid];

    // cp.async copy mapping
    const int xr  = tid >> 3;           // X rows 0..31 (+32 for 2nd copy)
    const int xk  = (tid & 7) * 4;      // k offset within BK
    const int wk  = tid >> 5;           // W k rows 0..7 (+8j)
    const int wn4 = (tid & 31) * 4;     // n offset

    const uint32_t xs_b  = (uint32_t)__cvta_generic_to_shared(Xs);
    const uint32_t was_b = (uint32_t)__cvta_generic_to_shared(Was);
    const uint32_t wbs_b = (uint32_t)__cvta_generic_to_shared(Wbs);

    float ca[2][4][4], cb[2][4][4];
    #pragma unroll
    for (int i = 0; i < 2; i++)
        #pragma unroll
        for (int j = 0; j < 4; j++)
            #pragma unroll
            for (int k = 0; k < 4; k++) { ca[i][j][k] = 0.f; cb[i][j][k] = 0.f; }

    auto issue = [&](int kt, int s) {
        const float* xg = X + (size_t)(row_base + xr) * LL + kt * BK + xk;
        cp_async16(xs_b + (uint32_t)(s*BM*XS_STR + xr*XS_STR + xk)*4u, xg);
        cp_async16(xs_b + (uint32_t)(s*BM*XS_STR + (xr+32)*XS_STR + xk)*4u, xg + (size_t)32*LL);
        #pragma unroll
        for (int j = 0; j < 4; j++) {
            const int k = wk + j*8;
            cp_async16(was_b + (uint32_t)(s*BK*WS_STR + k*WS_STR + wn4)*4u,
                       Wa + (size_t)(kt*BK + k)*DD + wn4);
            cp_async16(wbs_b + (uint32_t)(s*BK*WS_STR + k*WS_STR + wn4)*4u,
                       Wb + (size_t)(kt*BK + k)*DD + wn4);
        }
        asm volatile("cp.async.commit_group;\n");
    };

    issue(0, 0);
    for (int kt = 0; kt < NK; kt++) {
        const int s = kt & 1;
        if (kt + 1 < NK) {
            issue(kt + 1, s ^ 1);
            asm volatile("cp.async.wait_group 1;\n");
        } else {
            asm volatile("cp.async.wait_group 0;\n");
        }
        __syncthreads();

        const uint32_t* Xb  = Xs  + s*BM*XS_STR + (wm*32)*XS_STR;
        const uint32_t* WaB = Was + s*BK*WS_STR + wn*32;
        const uint32_t* WbB = Wbs + s*BK*WS_STR + wn*32;

        #pragma unroll
        for (int ks = 0; ks < 4; ks++) {
            const int k0 = ks * 8;
            uint32_t a[2][4];
            #pragma unroll
            for (int mt = 0; mt < 2; mt++) {
                const int r = mt*16 + g;
                a[mt][0] = Xb[(r    )*XS_STR + k0 + t    ];
                a[mt][1] = Xb[(r + 8)*XS_STR + k0 + t    ];
                a[mt][2] = Xb[(r    )*XS_STR + k0 + t + 4];
                a[mt][3] = Xb[(r + 8)*XS_STR + k0 + t + 4];
            }
            #pragma unroll
            for (int nt = 0; nt < 4; nt++) {
                const int n = nt*8 + g;
                uint32_t ba[2], bb[2];
                ba[0] = WaB[(k0 + t    )*WS_STR + n];
                ba[1] = WaB[(k0 + t + 4)*WS_STR + n];
                bb[0] = WbB[(k0 + t    )*WS_STR + n];
                bb[1] = WbB[(k0 + t + 4)*WS_STR + n];
                mma_tf32(ca[0][nt], a[0], ba);
                mma_tf32(ca[1][nt], a[1], ba);
                mma_tf32(cb[0][nt], a[0], bb);
                mma_tf32(cb[1][nt], a[1], bb);
            }
        }
        __syncthreads();
    }

    // Epilogue: v = tanh(ca)*sigmoid(cb); logit_row = sum_d v * Wc[d]
    #pragma unroll
    for (int mt = 0; mt < 2; mt++) {
        float p0 = 0.f, p1 = 0.f;
        #pragma unroll
        for (int nt = 0; nt < 4; nt++) {
            const int c0 = wn*32 + nt*8 + 2*t;
            const float wc0 = Wc_s[c0], wc1 = Wc_s[c0 + 1];
            p0 += tanhf(ca[mt][nt][0]) * (1.f/(1.f+expf(-cb[mt][nt][0]))) * wc0;
            p0 += tanhf(ca[mt][nt][1]) * (1.f/(1.f+expf(-cb[mt][nt][1]))) * wc1;
            p1 += tanhf(ca[mt][nt][2]) * (1.f/(1.f+expf(-cb[mt][nt][2]))) * wc0;
            p1 += tanhf(ca[mt][nt][3]) * (1.f/(1.f+expf(-cb[mt][nt][3]))) * wc1;
        }
        p0 += __shfl_xor_sync(0xffffffffu, p0, 1);
        p0 += __shfl_xor_sync(0xffffffffu, p0, 2);
        p1 += __shfl_xor_sync(0xffffffffu, p1, 1);
        p1 += __shfl_xor_sync(0xffffffffu, p1, 2);
        if (t == 0) {
            red[(wm*32 + mt*16 + g    )*4 + wn] = p0;
            red[(wm*32 + mt*16 + g + 8)*4 + wn] = p1;
        }
    }
    __syncthreads();
    if (tid < BM) {
        const float lg = red[tid*4+0] + red[tid*4+1] + red[tid*4+2] + red[tid*4+3];
        g_logits[row_base + tid] = lg;
    }
}

// ---------------------------------------------------------------------------
// Phase 2: per-batch masked softmax over N=8192 logits -> weights
// ---------------------------------------------------------------------------
__global__ void softmax_kernel(const void* __restrict__ mask)
{
    __shared__ float sdata[256];
    const int b = blockIdx.x, tid = threadIdx.x;
    const int mode = g_mask_mode;
    const float* lg = g_logits + b * NN;
    const int base = b * NN;

    float mx = -FLT_MAX;
    for (int i = tid; i < NN; i += 256)
        if (!is_pad(mask, mode, base + i)) mx = fmaxf(mx, lg[i]);
    sdata[tid] = mx; __syncthreads();
    for (int s2 = 128; s2 > 0; s2 >>= 1) {
        if (tid < s2) sdata[tid] = fmaxf(sdata[tid], sdata[tid + s2]);
        __syncthreads();
    }
    mx = sdata[0]; __syncthreads();

    float sum = 0.f;
    for (int i = tid; i < NN; i += 256)
        if (!is_pad(mask, mode, base + i)) sum += expf(lg[i] - mx);
    sdata[tid] = sum; __syncthreads();
    for (int s2 = 128; s2 > 0; s2 >>= 1) {
        if (tid < s2) sdata[tid] += sdata[tid + s2];
        __syncthreads();
    }
    const float inv = 1.f / sdata[0];

    for (int i = tid; i < NN; i += 256)
        g_weights[base + i] = is_pad(mask, mode, base + i) ? 0.f
                                                           : expf(lg[i] - mx) * inv;
}

// ---------------------------------------------------------------------------
// Phase 3: out_partial[b][chunk][l] = sum_{n in chunk} w[b,n] * x[b,n,l]
// Grid (4 col-tiles, 16 chunks, 8 batches) x 256 thr. Deterministic partials.
// ---------------------------------------------------------------------------
__global__ void weighted_sum_kernel(const float* __restrict__ X)
{
    __shared__ float ws[512];
    const int colt  = blockIdx.x;   // 0..3
    const int chunk = blockIdx.y;   // 0..15
    const int b     = blockIdx.z;   // 0..7
    const int tid   = threadIdx.x;
    const int col   = colt * 256 + tid;

    const float* w  = g_weights + b * NN + chunk * 512;
    ws[tid]       = w[tid];
    ws[tid + 256] = w[tid + 256];
    __syncthreads();

    const float* xb = X + ((size_t)b * NN + (size_t)chunk * 512) * LL;
    float acc = 0.f;
    #pragma unroll 8
    for (int r = 0; r < 512; r++)
        acc += ws[r] * xb[(size_t)r * LL + col];

    g_partial[(size_t)(b * CHUNKS + chunk) * LL + col] = acc;
}

// ---------------------------------------------------------------------------
// Phase 4: out[b][l] = sum_chunk partial[b][chunk][l]
// ---------------------------------------------------------------------------
__global__ void reduce_out_kernel(float* __restrict__ out)
{
    const int idx = blockIdx.x * 256 + threadIdx.x;  // 0..8191
    const int b = idx >> 10, l = idx & 1023;
    float s = 0.f;
    #pragma unroll
    for (int c = 0; c < CHUNKS; c++)
        s += g_partial[(size_t)(b * CHUNKS + c) * LL + l];
    out[idx] = s;
}

// ---------------------------------------------------------------------------
extern "C" void kernel_launch(void* const* d_in, const int* in_sizes, int n_in,
                              void* d_out, int out_size)
{
    // Identify inputs by element count (robust to ordering):
    //   x = 67108864, mask = 65536, Wa/Wb = 131072 (in order), Wc = 128
    const float* x    = nullptr;
    const void*  mask = nullptr;
    const float* Wa   = nullptr;
    const float* Wb   = nullptr;
    const float* Wc   = nullptr;
    for (int i = 0; i < n_in; i++) {
        const int sz = in_sizes[i];
        if (sz == M_TOTAL * LL)      x = (const float*)d_in[i];
        else if (sz == M_TOTAL)      mask = d_in[i];
        else if (sz == DD)           Wc = (const float*)d_in[i];
        else if (sz == LL * DD) {
            if (!Wa) Wa = (const float*)d_in[i];
            else     Wb = (const float*)d_in[i];
        }
    }
    float* out = (float*)d_out;

    cudaFuncSetAttribute(gemm_logits_kernel,
                         cudaFuncAttributeMaxDynamicSharedMemorySize, SMEM_BYTES);

    detect_mask_kernel<<<1, 1024>>>((const uint32_t*)mask);
    gemm_logits_kernel<<<M_TOTAL / BM, 256, SMEM_BYTES>>>(x, Wa, Wb, Wc);
    softmax_kernel<<<BB, 256>>>(mask);
    dim3 g3(LL / 256, CHUNKS, BB);
    weighted_sum_kernel<<<g3, 256>>>(x);
    reduce_out_kernel<<<(BB * LL) / 256, 256>>>(out);
}

// round 14
// speedup vs baseline: 1.0024x; 1.0024x over previous
#include <cuda_runtime.h>
#include <cstdint>
#include <cfloat>
#include <cmath>

// Problem shape (fixed by reference)
constexpr int BB = 8, NN = 8192, LL = 1024, DD = 128;
constexpr int M_TOTAL = BB * NN;            // 65536 rows
constexpr int BM = 64, BK = 32;
constexpr int NK = LL / BK;                 // 32 k-tiles
constexpr int XS_STR = 36;                  // 4g+t distinct mod 32 -> conflict-free A-frag LDS
constexpr int WS_STR = 136;                 // 8t+g distinct mod 32 -> conflict-free B-frag LDS
constexpr int XS_ELEMS = 2 * BM * XS_STR;   // 4608 words
constexpr int WS_ELEMS = 2 * BK * WS_STR;   // 8704 words
constexpr int SMEM_WORDS = XS_ELEMS + 2 * WS_ELEMS + DD + BM * 4;
constexpr int SMEM_BYTES = SMEM_WORDS * 4;  // 89600 B -> 2 CTAs/SM

constexpr int CHUNKS = 16;                  // n-chunks per batch for deterministic pooling

// Scratch (no allocation allowed in kernel_launch)
__device__ float g_logits[M_TOTAL];
__device__ float g_weights[M_TOTAL];
__device__ float g_partial[BB * CHUNKS * LL];
__device__ int   g_mask_mode;               // 0=int32, 1=float32, 2=int8

__device__ __forceinline__ void cp_async16(uint32_t s, const void* g) {
    asm volatile("cp.async.cg.shared.global [%0], [%1], 16;\n" :: "r"(s), "l"(g));
}

__device__ __forceinline__ void mma_tf32(float* c, const uint32_t* a, const uint32_t* b) {
    asm volatile(
        "mma.sync.aligned.m16n8k8.row.col.f32.tf32.tf32.f32 "
        "{%0,%1,%2,%3}, {%4,%5,%6,%7}, {%8,%9}, {%0,%1,%2,%3};\n"
        : "+f"(c[0]), "+f"(c[1]), "+f"(c[2]), "+f"(c[3])
        : "r"(a[0]), "r"(a[1]), "r"(a[2]), "r"(a[3]), "r"(b[0]), "r"(b[1]));
}

// ---------------------------------------------------------------------------
// Phase 0: detect the mask dtype from its bit pattern (deterministic).
// Scan the first 16384 32-bit words (64 KB = full buffer if int8, first
// quarter if int32/float32). Mask semantics guarantee runs of >=4096
// consecutive 1s per batch, so:
//   all words in {0,1}        -> int32 (mode 0)
//   any word == 0x3F800000   -> float32 (mode 1)
//   otherwise                 -> int8  (mode 2)
// ---------------------------------------------------------------------------
__global__ void detect_mask_kernel(const uint32_t* __restrict__ m)
{
    __shared__ int s_non01, s_f32;
    if (threadIdx.x == 0) { s_non01 = 0; s_f32 = 0; }
    __syncthreads();
    int non01 = 0, isf32 = 0;
    for (int i = threadIdx.x; i < 16384; i += blockDim.x) {
        const uint32_t w = m[i];
        if (w > 1u) non01 = 1;
        if (w == 0x3F800000u) isf32 = 1;
    }
    if (non01) atomicOr(&s_non01, 1);
    if (isf32) atomicOr(&s_f32, 1);
    __syncthreads();
    if (threadIdx.x == 0)
        g_mask_mode = (!s_non01) ? 0 : (s_f32 ? 1 : 2);
}

__device__ __forceinline__ bool is_pad(const void* mask, int mode, int idx) {
    if (mode == 0) return ((const int*)mask)[idx] != 0;
    if (mode == 1) return ((const float*)mask)[idx] != 0.0f;
    return ((const unsigned char*)mask)[idx] != 0;
}

// ---------------------------------------------------------------------------
// Phase 1: fused  Ca = X@Wa, Cb = X@Wb, logit = (tanh(Ca)*sigmoid(Cb)) @ Wc
// Grid: 1024 CTAs x 256 thr. CTA tile: 64(M) x 128(D) x full K=1024.
// 8 warps as 2(M) x 4(N), each warp 32x32 per GEMM.
// ---------------------------------------------------------------------------
__global__ void __launch_bounds__(256, 2)
gemm_logits_kernel(const float* __restrict__ X, const float* __restrict__ Wa,
                   const float* __restrict__ Wb, const float* __restrict__ Wc)
{
    extern __shared__ uint32_t sm[];
    uint32_t* Xs  = sm;                       // [2][64][36]
    uint32_t* Was = sm + XS_ELEMS;            // [2][32][136]
    uint32_t* Wbs = Was + WS_ELEMS;           // [2][32][136]
    float* Wc_s   = (float*)(Wbs + WS_ELEMS); // [128]
    float* red    = Wc_s + DD;                // [64][4]

    const int tid  = threadIdx.x;
    const int lane = tid & 31;
    const int warp = tid >> 5;
    const int g = lane >> 2, t = lane & 3;
    const int wm = warp >> 2, wn = warp & 3;
    const int row_base = blockIdx.x * BM;

    if (tid < DD) Wc_s[tid] = Wc[tid];

    // cp.async copy mapping
    const int xr  = tid >> 3;           // X rows 0..31 (+32 for 2nd copy)
    const int xk  = (tid & 7) * 4;      // k offset within BK
    const int wk  = tid >> 5;           // W k rows 0..7 (+8j)
    const int wn4 = (tid & 31) * 4;     // n offset

    const uint32_t xs_b  = (uint32_t)__cvta_generic_to_shared(Xs);
    const uint32_t was_b = (uint32_t)__cvta_generic_to_shared(Was);
    const uint32_t wbs_b = (uint32_t)__cvta_generic_to_shared(Wbs);

    float ca[2][4][4], cb[2][4][4];
    #pragma unroll
    for (int i = 0; i < 2; i++)
        #pragma unroll
        for (int j = 0; j < 4; j++)
            #pragma unroll
            for (int k = 0; k < 4; k++) { ca[i][j][k] = 0.f; cb[i][j][k] = 0.f; }

    auto issue = [&](int kt, int s) {
        const float* xg = X + (size_t)(row_base + xr) * LL + kt * BK + xk;
        cp_async16(xs_b + (uint32_t)(s*BM*XS_STR + xr*XS_STR + xk)*4u, xg);
        cp_async16(xs_b + (uint32_t)(s*BM*XS_STR + (xr+32)*XS_STR + xk)*4u, xg + (size_t)32*LL);
        #pragma unroll
        for (int j = 0; j < 4; j++) {
            const int k = wk + j*8;
            cp_async16(was_b + (uint32_t)(s*BK*WS_STR + k*WS_STR + wn4)*4u,
                       Wa + (size_t)(kt*BK + k)*DD + wn4);
            cp_async16(wbs_b + (uint32_t)(s*BK*WS_STR + k*WS_STR + wn4)*4u,
                       Wb + (size_t)(kt*BK + k)*DD + wn4);
        }
        asm volatile("cp.async.commit_group;\n");
    };

    issue(0, 0);
    for (int kt = 0; kt < NK; kt++) {
        const int s = kt & 1;
        if (kt + 1 < NK) {
            issue(kt + 1, s ^ 1);
            asm volatile("cp.async.wait_group 1;\n");
        } else {
            asm volatile("cp.async.wait_group 0;\n");
        }
        __syncthreads();

        const uint32_t* Xb  = Xs  + s*BM*XS_STR + (wm*32)*XS_STR;
        const uint32_t* WaB = Was + s*BK*WS_STR + wn*32;
        const uint32_t* WbB = Wbs + s*BK*WS_STR + wn*32;

        #pragma unroll
        for (int ks = 0; ks < 4; ks++) {
            const int k0 = ks * 8;
            uint32_t a[2][4];
            #pragma unroll
            for (int mt = 0; mt < 2; mt++) {
                const int r = mt*16 + g;
                a[mt][0] = Xb[(r    )*XS_STR + k0 + t    ];
                a[mt][1] = Xb[(r + 8)*XS_STR + k0 + t    ];
                a[mt][2] = Xb[(r    )*XS_STR + k0 + t + 4];
                a[mt][3] = Xb[(r + 8)*XS_STR + k0 + t + 4];
            }
            #pragma unroll
            for (int nt = 0; nt < 4; nt++) {
                const int n = nt*8 + g;
                uint32_t ba[2], bb[2];
                ba[0] = WaB[(k0 + t    )*WS_STR + n];
                ba[1] = WaB[(k0 + t + 4)*WS_STR + n];
                bb[0] = WbB[(k0 + t    )*WS_STR + n];
                bb[1] = WbB[(k0 + t + 4)*WS_STR + n];
                mma_tf32(ca[0][nt], a[0], ba);
                mma_tf32(ca[1][nt], a[1], ba);
                mma_tf32(cb[0][nt], a[0], bb);
                mma_tf32(cb[1][nt], a[1], bb);
            }
        }
        __syncthreads();
    }

    // Epilogue: v = tanh(ca)*sigmoid(cb); logit_row = sum_d v * Wc[d]
    #pragma unroll
    for (int mt = 0; mt < 2; mt++) {
        float p0 = 0.f, p1 = 0.f;
        #pragma unroll
        for (int nt = 0; nt < 4; nt++) {
            const int c0 = wn*32 + nt*8 + 2*t;
            const float wc0 = Wc_s[c0], wc1 = Wc_s[c0 + 1];
            p0 += tanhf(ca[mt][nt][0]) * (1.f/(1.f+expf(-cb[mt][nt][0]))) * wc0;
            p0 += tanhf(ca[mt][nt][1]) * (1.f/(1.f+expf(-cb[mt][nt][1]))) * wc1;
            p1 += tanhf(ca[mt][nt][2]) * (1.f/(1.f+expf(-cb[mt][nt][2]))) * wc0;
            p1 += tanhf(ca[mt][nt][3]) * (1.f/(1.f+expf(-cb[mt][nt][3]))) * wc1;
        }
        p0 += __shfl_xor_sync(0xffffffffu, p0, 1);
        p0 += __shfl_xor_sync(0xffffffffu, p0, 2);
        p1 += __shfl_xor_sync(0xffffffffu, p1, 1);
        p1 += __shfl_xor_sync(0xffffffffu, p1, 2);
        if (t == 0) {
            red[(wm*32 + mt*16 + g    )*4 + wn] = p0;
            red[(wm*32 + mt*16 + g + 8)*4 + wn] = p1;
        }
    }
    __syncthreads();
    if (tid < BM) {
        const float lg = red[tid*4+0] + red[tid*4+1] + red[tid*4+2] + red[tid*4+3];
        g_logits[row_base + tid] = lg;
    }
}

// ---------------------------------------------------------------------------
// Phase 2: per-batch masked softmax over N=8192 logits -> weights
// ---------------------------------------------------------------------------
__global__ void softmax_kernel(const void* __restrict__ mask)
{
    __shared__ float sdata[256];
    const int b = blockIdx.x, tid = threadIdx.x;
    const int mode = g_mask_mode;
    const float* lg = g_logits + b * NN;
    const int base = b * NN;

    float mx = -FLT_MAX;
    for (int i = tid; i < NN; i += 256)
        if (!is_pad(mask, mode, base + i)) mx = fmaxf(mx, lg[i]);
    sdata[tid] = mx; __syncthreads();
    for (int s2 = 128; s2 > 0; s2 >>= 1) {
        if (tid < s2) sdata[tid] = fmaxf(sdata[tid], sdata[tid + s2]);
        __syncthreads();
    }
    mx = sdata[0]; __syncthreads();

    float sum = 0.f;
    for (int i = tid; i < NN; i += 256)
        if (!is_pad(mask, mode, base + i)) sum += expf(lg[i] - mx);
    sdata[tid] = sum; __syncthreads();
    for (int s2 = 128; s2 > 0; s2 >>= 1) {
        if (tid < s2) sdata[tid] += sdata[tid + s2];
        __syncthreads();
    }
    const float inv = 1.f / sdata[0];

    for (int i = tid; i < NN; i += 256)
        g_weights[base + i] = is_pad(mask, mode, base + i) ? 0.f
                                                           : expf(lg[i] - mx) * inv;
}

// ---------------------------------------------------------------------------
// Phase 3: out_partial[b][chunk][l] = sum_{n in chunk} w[b,n] * x[b,n,l]
// Grid (4 col-tiles, 16 chunks, 8 batches) x 256 thr. Deterministic partials.
// ---------------------------------------------------------------------------
__global__ void weighted_sum_kernel(const float* __restrict__ X)
{
    __shared__ float ws[512];
    const int colt  = blockIdx.x;   // 0..3
    const int chunk = blockIdx.y;   // 0..15
    const int b     = blockIdx.z;   // 0..7
    const int tid   = threadIdx.x;
    const int col   = colt * 256 + tid;

    const float* w  = g_weights + b * NN + chunk * 512;
    ws[tid]       = w[tid];
    ws[tid + 256] = w[tid + 256];
    __syncthreads();

    const float* xb = X + ((size_t)b * NN + (size_t)chunk * 512) * LL;
    float acc = 0.f;
    #pragma unroll 8
    for (int r = 0; r < 512; r++)
        acc += ws[r] * xb[(size_t)r * LL + col];

    g_partial[(size_t)(b * CHUNKS + chunk) * LL + col] = acc;
}

// ---------------------------------------------------------------------------
// Phase 4: out[b][l] = sum_chunk partial[b][chunk][l]
// ---------------------------------------------------------------------------
__global__ void reduce_out_kernel(float* __restrict__ out)
{
    const int idx = blockIdx.x * 256 + threadIdx.x;  // 0..8191
    const int b = idx >> 10, l = idx & 1023;
    float s = 0.f;
    #pragma unroll
    for (int c = 0; c < CHUNKS; c++)
        s += g_partial[(size_t)(b * CHUNKS + c) * LL + l];
    out[idx] = s;
}

// ---------------------------------------------------------------------------
extern "C" void kernel_launch(void* const* d_in, const int* in_sizes, int n_in,
                              void* d_out, int out_size)
{
    // Identify inputs by element count (robust to ordering):
    //   x = 67108864, mask = 65536, Wa/Wb = 131072 (in order), Wc = 128
    const float* x    = nullptr;
    const void*  mask = nullptr;
    const float* Wa   = nullptr;
    const float* Wb   = nullptr;
    const float* Wc   = nullptr;
    for (int i = 0; i < n_in; i++) {
        const int sz = in_sizes[i];
        if (sz == M_TOTAL * LL)      x = (const float*)d_in[i];
        else if (sz == M_TOTAL)      mask = d_in[i];
        else if (sz == DD)           Wc = (const float*)d_in[i];
        else if (sz == LL * DD) {
            if (!Wa) Wa = (const float*)d_in[i];
            else     Wb = (const float*)d_in[i];
        }
    }
    float* out = (float*)d_out;

    cudaFuncSetAttribute(gemm_logits_kernel,
                         cudaFuncAttributeMaxDynamicSharedMemorySize, SMEM_BYTES);

    detect_mask_kernel<<<1, 1024>>>((const uint32_t*)mask);
    gemm_logits_kernel<<<M_TOTAL / BM, 256, SMEM_BYTES>>>(x, Wa, Wb, Wc);
    softmax_kernel<<<BB, 256>>>(mask);
    dim3 g3(LL / 256, CHUNKS, BB);
    weighted_sum_kernel<<<g3, 256>>>(x);
    reduce_out_kernel<<<(BB * LL) / 256, 256>>>(out);
}